// round 1
// baseline (speedup 1.0000x reference)
#include <cuda_runtime.h>
#include <math.h>

// ---------------------------------------------------------------------------
// Problem constants (fixed by the reference)
// ---------------------------------------------------------------------------
#define NN     50000
#define EE     400000
#define F_IN   128
#define H0     4
#define C0     64
#define F0     (H0*C0)    // 256
#define H1     1
#define C1     256
#define F1     256
#define NCLS   10
#define SLOPE  0.2f

// ---------------------------------------------------------------------------
// Scratch (device globals -- no allocations allowed)
// ---------------------------------------------------------------------------
__device__ float g_h   [NN * 256];          // h (x@W) for current GAT layer
__device__ float g_out [NN * 256];          // layer0 aggregation output
__device__ float g_out2[NN * 256];          // layer1 aggregation output
__device__ float g_t1  [NN * 512];          // mlp hidden 1
__device__ float g_t2  [NN * 1024];         // mlp hidden 2
__device__ float g_asrc[NN * H0];
__device__ float g_adst[NN * H0];
__device__ float g_emax[NN * H0];
__device__ float g_denom[NN * H0];
__device__ float g_escr[(EE + NN) * H0];    // per-edge e, then per-edge w

// ---------------------------------------------------------------------------
// Helpers
// ---------------------------------------------------------------------------
__device__ __forceinline__ void atomicMaxFloat(float* addr, float v) {
    if (v >= 0.0f) atomicMax((int*)addr, __float_as_int(v));
    else           atomicMin((unsigned int*)addr, __float_as_uint(v));
}

__device__ __forceinline__ void redAddF4(float* p, float4 r) {
    asm volatile("red.global.add.v4.f32 [%0], {%1,%2,%3,%4};"
                 :: "l"(p), "f"(r.x), "f"(r.y), "f"(r.z), "f"(r.w) : "memory");
}

// ---------------------------------------------------------------------------
// SGEMM: C[M,N] = A[M,K] @ B[K,N]  (+bias, +relu)   A,B,C row-major
// 128x128 block tile, BK=8, 256 threads, 8x8 per-thread microtile.
// N multiple of 128, K multiple of 8; M guarded.
// ---------------------------------------------------------------------------
#define BM 128
#define BN 128
#define BK 8
#define TM 8
#define TN 8

__global__ __launch_bounds__(256) void sgemm_kernel(
    int M, int N, int K,
    const float* __restrict__ A, const float* __restrict__ B,
    const float* __restrict__ bias, float* __restrict__ C, int do_relu)
{
    __shared__ float As[BK][BM];
    __shared__ float Bs[BK][BN];

    const int tid  = threadIdx.x;
    const int crow = tid / (BN / TN);     // 0..15
    const int ccol = tid % (BN / TN);     // 0..15
    const int rowBase = blockIdx.y * BM;
    const int colBase = blockIdx.x * BN;

    const int arow = tid >> 1;            // 0..127
    const int acol = (tid & 1) << 2;      // 0 or 4
    const int brow = tid >> 5;            // 0..7
    const int bcol = (tid & 31) << 2;     // 0..124

    float acc[TM][TN];
    #pragma unroll
    for (int i = 0; i < TM; i++)
        #pragma unroll
        for (int j = 0; j < TN; j++) acc[i][j] = 0.0f;

    const bool aValid = (rowBase + arow) < M;
    const float* Aptr = A + (size_t)(rowBase + arow) * K + acol;
    const float* Bptr = B + (size_t)brow * N + colBase + bcol;

    for (int k0 = 0; k0 < K; k0 += BK) {
        float4 av = aValid ? *(const float4*)Aptr : make_float4(0.f,0.f,0.f,0.f);
        float4 bv = *(const float4*)Bptr;
        Aptr += BK;
        Bptr += (size_t)BK * N;

        As[acol + 0][arow] = av.x;
        As[acol + 1][arow] = av.y;
        As[acol + 2][arow] = av.z;
        As[acol + 3][arow] = av.w;
        *(float4*)&Bs[brow][bcol] = bv;
        __syncthreads();

        #pragma unroll
        for (int k = 0; k < BK; k++) {
            float regM[TM], regN[TN];
            #pragma unroll
            for (int i = 0; i < TM; i++) regM[i] = As[k][crow * TM + i];
            #pragma unroll
            for (int j = 0; j < TN; j++) regN[j] = Bs[k][ccol * TN + j];
            #pragma unroll
            for (int i = 0; i < TM; i++)
                #pragma unroll
                for (int j = 0; j < TN; j++)
                    acc[i][j] = fmaf(regM[i], regN[j], acc[i][j]);
        }
        __syncthreads();
    }

    #pragma unroll
    for (int i = 0; i < TM; i++) {
        int row = rowBase + crow * TM + i;
        if (row >= M) continue;
        #pragma unroll
        for (int j = 0; j < TN; j += 4) {
            int col = colBase + ccol * TN + j;
            float4 v = make_float4(acc[i][j], acc[i][j+1], acc[i][j+2], acc[i][j+3]);
            if (bias) {
                v.x += bias[col];   v.y += bias[col+1];
                v.z += bias[col+2]; v.w += bias[col+3];
            }
            if (do_relu) {
                v.x = fmaxf(v.x, 0.f); v.y = fmaxf(v.y, 0.f);
                v.z = fmaxf(v.z, 0.f); v.w = fmaxf(v.w, 0.f);
            }
            *(float4*)&C[(size_t)row * N + col] = v;
        }
    }
}

// ---------------------------------------------------------------------------
// alpha_src/alpha_dst per (node, head); also init emax/denom.
// One warp per (node, head).
// ---------------------------------------------------------------------------
__global__ void alpha_init_kernel(
    const float* __restrict__ h, const float* __restrict__ a_src,
    const float* __restrict__ a_dst, int Nn, int H, int C,
    float* __restrict__ asrc, float* __restrict__ adst,
    float* __restrict__ emax, float* __restrict__ denom)
{
    int idx  = (blockIdx.x * blockDim.x + threadIdx.x) >> 5;
    int lane = threadIdx.x & 31;
    if (idx >= Nn * H) return;
    int node = idx / H;
    int head = idx % H;

    const float* hp = h + (size_t)node * H * C + head * C;
    const float* as = a_src + head * C;
    const float* ad = a_dst + head * C;
    float s1 = 0.f, s2 = 0.f;
    for (int c = lane; c < C; c += 32) {
        float v = hp[c];
        s1 = fmaf(v, as[c], s1);
        s2 = fmaf(v, ad[c], s2);
    }
    #pragma unroll
    for (int off = 16; off; off >>= 1) {
        s1 += __shfl_xor_sync(0xffffffffu, s1, off);
        s2 += __shfl_xor_sync(0xffffffffu, s2, off);
    }
    if (lane == 0) {
        asrc[idx]  = s1;
        adst[idx]  = s2;
        emax[idx]  = -1e30f;
        denom[idx] = 0.f;
    }
}

// ---------------------------------------------------------------------------
// Pass 1 over edges: e = leaky_relu(asrc[src]+adst[dst]); segment max into emax.
// Edges [0,E): from edge_index (valid iff src!=dst). Edges [E,E+Nn): self-loops.
// ---------------------------------------------------------------------------
__global__ void edge_max_kernel(
    const int* __restrict__ ei, int E, int Nn, int H,
    const float* __restrict__ asrc, const float* __restrict__ adst,
    float* __restrict__ escr, float* __restrict__ emax)
{
    int i = blockIdx.x * blockDim.x + threadIdx.x;
    int tot = E + Nn;
    if (i >= tot) return;
    int s, d; bool valid;
    if (i < E) { s = ei[i]; d = ei[E + i]; valid = (s != d); }
    else       { s = d = i - E; valid = true; }

    for (int h = 0; h < H; h++) {
        float e = -1e30f;
        if (valid) {
            float v = asrc[s * H + h] + adst[d * H + h];
            e = (v > 0.f) ? v : SLOPE * v;
            atomicMaxFloat(&emax[d * H + h], e);
        }
        escr[(size_t)i * H + h] = e;
    }
}

// ---------------------------------------------------------------------------
// Pass 2: w = exp(e - emax[dst]); segment sum into denom; store w back.
// ---------------------------------------------------------------------------
__global__ void edge_denom_kernel(
    const int* __restrict__ ei, int E, int Nn, int H,
    const float* __restrict__ emax,
    float* __restrict__ escr, float* __restrict__ denom)
{
    int i = blockIdx.x * blockDim.x + threadIdx.x;
    int tot = E + Nn;
    if (i >= tot) return;
    int d = (i < E) ? ei[E + i] : (i - E);
    for (int h = 0; h < H; h++) {
        float w = expf(escr[(size_t)i * H + h] - emax[d * H + h]);
        escr[(size_t)i * H + h] = w;
        if (w != 0.f) atomicAdd(&denom[d * H + h], w);
    }
}

// ---------------------------------------------------------------------------
// Pass 3: out[dst] += (w/denom[dst]) * h[src]   (vector atomics, warp per edge)
// F = H*C = 256 for both layers.
// ---------------------------------------------------------------------------
__global__ void edge_aggregate_kernel(
    const int* __restrict__ ei, int E, int Nn, int H, int C,
    const float* __restrict__ w_e, const float* __restrict__ denom,
    const float* __restrict__ hfeat, float* __restrict__ out)
{
    int gw   = (blockIdx.x * blockDim.x + threadIdx.x) >> 5;
    int lane = threadIdx.x & 31;
    int tot = E + Nn;
    if (gw >= tot) return;
    int s, d;
    if (gw < E) { s = ei[gw]; d = ei[E + gw]; } else { s = d = gw - E; }

    const int F  = H * C;       // 256
    const int Q  = F / 4;       // 64 float4 chunks
    const float* hs = hfeat + (size_t)s * F;
    float* op = out + (size_t)d * F;

    for (int q = lane; q < Q; q += 32) {
        int col  = q * 4;
        int head = col / C;
        float w = w_e[(size_t)gw * H + head];
        float coef = w / denom[d * H + head];
        float4 hv = *(const float4*)&hs[col];
        float4 r  = make_float4(hv.x * coef, hv.y * coef, hv.z * coef, hv.w * coef);
        redAddF4(&op[col], r);
    }
}

// ---------------------------------------------------------------------------
// x[n, c] = relu(x[n, c] + b[c]) for F=256 (float4 vectorized)
// ---------------------------------------------------------------------------
__global__ void bias_relu_kernel(float4* __restrict__ x,
                                 const float* __restrict__ b, int total4)
{
    int i = blockIdx.x * blockDim.x + threadIdx.x;
    if (i >= total4) return;
    int c = (i & 63) * 4;   // F/4 = 64 chunks per row
    float4 v = x[i];
    v.x = fmaxf(v.x + b[c + 0], 0.f);
    v.y = fmaxf(v.y + b[c + 1], 0.f);
    v.z = fmaxf(v.z + b[c + 2], 0.f);
    v.w = fmaxf(v.w + b[c + 3], 0.f);
    x[i] = v;
}

// ---------------------------------------------------------------------------
// Final: out = softmax(relu(X @ lw3 + lb3)), X:[N,1024], lw3:[1024,10]
// One block (128 threads) per node.
// ---------------------------------------------------------------------------
__global__ __launch_bounds__(128) void final_kernel(
    const float* __restrict__ X, const float* __restrict__ W,
    const float* __restrict__ b, float* __restrict__ out, int K)
{
    int n = blockIdx.x;
    const float* x = X + (size_t)n * K;

    float acc[NCLS];
    #pragma unroll
    for (int c = 0; c < NCLS; c++) acc[c] = 0.f;

    for (int k = threadIdx.x; k < K; k += 128) {
        float xv = x[k];
        const float* wr = W + (size_t)k * NCLS;
        #pragma unroll
        for (int c = 0; c < NCLS; c++) acc[c] = fmaf(xv, wr[c], acc[c]);
    }
    #pragma unroll
    for (int c = 0; c < NCLS; c++)
        #pragma unroll
        for (int off = 16; off; off >>= 1)
            acc[c] += __shfl_xor_sync(0xffffffffu, acc[c], off);

    __shared__ float sm[4][NCLS];
    int warp = threadIdx.x >> 5, lane = threadIdx.x & 31;
    if (lane == 0) {
        #pragma unroll
        for (int c = 0; c < NCLS; c++) sm[warp][c] = acc[c];
    }
    __syncthreads();
    if (threadIdx.x == 0) {
        float logits[NCLS];
        float m = -1e30f;
        #pragma unroll
        for (int c = 0; c < NCLS; c++) {
            float v = sm[0][c] + sm[1][c] + sm[2][c] + sm[3][c] + b[c];
            v = fmaxf(v, 0.f);
            logits[c] = v;
            m = fmaxf(m, v);
        }
        float ssum = 0.f;
        #pragma unroll
        for (int c = 0; c < NCLS; c++) { logits[c] = expf(logits[c] - m); ssum += logits[c]; }
        float inv = 1.f / ssum;
        #pragma unroll
        for (int c = 0; c < NCLS; c++) out[(size_t)n * NCLS + c] = logits[c] * inv;
    }
}

// ---------------------------------------------------------------------------
// Launch
// ---------------------------------------------------------------------------
static inline int ceil_div(int a, int b) { return (a + b - 1) / b; }

extern "C" void kernel_launch(void* const* d_in, const int* in_sizes, int n_in,
                              void* d_out, int out_size)
{
    const float* x      = (const float*)d_in[0];
    const int*   ei     = (const int*)  d_in[1];
    const float* W0     = (const float*)d_in[2];
    const float* a_src0 = (const float*)d_in[3];
    const float* a_dst0 = (const float*)d_in[4];
    const float* b0     = (const float*)d_in[5];
    const float* W1     = (const float*)d_in[6];
    const float* a_src1 = (const float*)d_in[7];
    const float* a_dst1 = (const float*)d_in[8];
    const float* b1     = (const float*)d_in[9];
    const float* lw1    = (const float*)d_in[10];
    const float* lb1    = (const float*)d_in[11];
    const float* lw2    = (const float*)d_in[12];
    const float* lb2    = (const float*)d_in[13];
    const float* lw3    = (const float*)d_in[14];
    const float* lb3    = (const float*)d_in[15];
    float* out = (float*)d_out;

    const int Nn = in_sizes[0] / F_IN;     // 50000
    const int E  = in_sizes[1] / 2;        // 400000
    const int tot = E + Nn;

    float *p_h, *p_out, *p_out2, *p_t1, *p_t2;
    float *p_asrc, *p_adst, *p_emax, *p_denom, *p_escr;
    cudaGetSymbolAddress((void**)&p_h,     g_h);
    cudaGetSymbolAddress((void**)&p_out,   g_out);
    cudaGetSymbolAddress((void**)&p_out2,  g_out2);
    cudaGetSymbolAddress((void**)&p_t1,    g_t1);
    cudaGetSymbolAddress((void**)&p_t2,    g_t2);
    cudaGetSymbolAddress((void**)&p_asrc,  g_asrc);
    cudaGetSymbolAddress((void**)&p_adst,  g_adst);
    cudaGetSymbolAddress((void**)&p_emax,  g_emax);
    cudaGetSymbolAddress((void**)&p_denom, g_denom);
    cudaGetSymbolAddress((void**)&p_escr,  g_escr);

    const int gy = ceil_div(Nn, BM);

    // ---------------- GAT layer 0 ----------------
    // h0 = x @ W0   [Nn,128]x[128,256]
    sgemm_kernel<<<dim3(F0 / BN, gy), 256>>>(Nn, F0, F_IN, x, W0, nullptr, p_h, 0);
    alpha_init_kernel<<<ceil_div(Nn * H0 * 32, 256), 256>>>(
        p_h, a_src0, a_dst0, Nn, H0, C0, p_asrc, p_adst, p_emax, p_denom);
    edge_max_kernel<<<ceil_div(tot, 256), 256>>>(ei, E, Nn, H0, p_asrc, p_adst, p_escr, p_emax);
    edge_denom_kernel<<<ceil_div(tot, 256), 256>>>(ei, E, Nn, H0, p_emax, p_escr, p_denom);
    cudaMemsetAsync(p_out, 0, (size_t)Nn * F0 * sizeof(float), 0);
    edge_aggregate_kernel<<<ceil_div(tot * 32, 256), 256>>>(
        ei, E, Nn, H0, C0, p_escr, p_denom, p_h, p_out);
    bias_relu_kernel<<<ceil_div(Nn * F0 / 4, 256), 256>>>((float4*)p_out, b0, Nn * F0 / 4);

    // ---------------- GAT layer 1 ----------------
    // h1 = out0 @ W1  [Nn,256]x[256,256]
    sgemm_kernel<<<dim3(F1 / BN, gy), 256>>>(Nn, F1, F0, p_out, W1, nullptr, p_h, 0);
    alpha_init_kernel<<<ceil_div(Nn * H1 * 32, 256), 256>>>(
        p_h, a_src1, a_dst1, Nn, H1, C1, p_asrc, p_adst, p_emax, p_denom);
    edge_max_kernel<<<ceil_div(tot, 256), 256>>>(ei, E, Nn, H1, p_asrc, p_adst, p_escr, p_emax);
    edge_denom_kernel<<<ceil_div(tot, 256), 256>>>(ei, E, Nn, H1, p_emax, p_escr, p_denom);
    cudaMemsetAsync(p_out2, 0, (size_t)Nn * F1 * sizeof(float), 0);
    edge_aggregate_kernel<<<ceil_div(tot * 32, 256), 256>>>(
        ei, E, Nn, H1, C1, p_escr, p_denom, p_h, p_out2);
    bias_relu_kernel<<<ceil_div(Nn * F1 / 4, 256), 256>>>((float4*)p_out2, b1, Nn * F1 / 4);

    // ---------------- MLP ----------------
    // t1 = relu(out1 @ lw1 + lb1)  [Nn,256]x[256,512]
    sgemm_kernel<<<dim3(512 / BN, gy), 256>>>(Nn, 512, 256, p_out2, lw1, lb1, p_t1, 1);
    // t2 = relu(t1 @ lw2 + lb2)    [Nn,512]x[512,1024]
    sgemm_kernel<<<dim3(1024 / BN, gy), 256>>>(Nn, 1024, 512, p_t1, lw2, lb2, p_t2, 1);
    // out = softmax(relu(t2 @ lw3 + lb3))
    final_kernel<<<Nn, 128>>>(p_t2, lw3, lb3, out, 1024);
}

// round 4
// speedup vs baseline: 1.2389x; 1.2389x over previous
#include <cuda_runtime.h>
#include <math.h>
#include <stdint.h>

// ---------------------------------------------------------------------------
// Problem constants
// ---------------------------------------------------------------------------
#define NN     50000
#define EE     400000
#define F_IN   128
#define H0     4
#define C0     64
#define F0     (H0*C0)    // 256
#define H1     1
#define C1     256
#define F1     256
#define NCLS   10
#define SLOPE  0.2f

// ---------------------------------------------------------------------------
// Scratch (device globals)
// ---------------------------------------------------------------------------
__device__ float g_h   [NN * 256];
__device__ float g_out [NN * 256];
__device__ float g_out2[NN * 256];
__device__ float g_t1  [NN * 512];
__device__ float g_t2  [NN * 1024];
__device__ float g_asrc[NN * H0];
__device__ float g_adst[NN * H0];
__device__ float g_emax[NN * H0];
__device__ float g_denom[NN * H0];
__device__ float g_escr[(EE + NN) * H0];
// transposed weights [N,K]
__device__ float g_wt0[256 * 128];
__device__ float g_wt1[256 * 256];
__device__ float g_wt2[512 * 256];
__device__ float g_wt3[1024 * 512];

// ---------------------------------------------------------------------------
// tf32 helpers (baseline PTX, sm_80+; NO sm_100a-only instructions)
// ---------------------------------------------------------------------------
__device__ __forceinline__ uint32_t f2tf32(float x) {
    uint32_t r;
    asm("cvt.rna.tf32.f32 %0, %1;" : "=r"(r) : "f"(x));
    return r;
}

__device__ __forceinline__ void mma8(float c[4], const uint32_t a[4],
                                     uint32_t b0, uint32_t b1) {
    asm volatile(
        "mma.sync.aligned.m16n8k8.row.col.f32.tf32.tf32.f32 "
        "{%0,%1,%2,%3}, {%4,%5,%6,%7}, {%8,%9}, {%0,%1,%2,%3};"
        : "+f"(c[0]), "+f"(c[1]), "+f"(c[2]), "+f"(c[3])
        : "r"(a[0]), "r"(a[1]), "r"(a[2]), "r"(a[3]), "r"(b0), "r"(b1));
}

// ---------------------------------------------------------------------------
// TF32x3 tensor-core GEMM:  C[M,N] = A[M,K] @ Bt[N,K]^T  (+bias, +relu)
// CTA tile 128x128, BK=32, 256 threads (8 warps, 2x4), warp tile 64x32.
// 3x compensation: ah*bh + ah*bl + al*bh  (fp32-level accuracy).
// N % 128 == 0, K % 32 == 0; M guarded.
// SMEM rows padded to 36 floats -> all fragment LDS are bank-conflict-free.
// ---------------------------------------------------------------------------
#define PAD   36
#define TILEW (128 * PAD)            // words per tile
#define GEMM_SMEM_BYTES (4 * TILEW * 4)   // Ah, Al, Bh, Bl = 73728 B

__global__ __launch_bounds__(256, 2)
void mma_gemm(int M, int N, int K,
              const float* __restrict__ A,    // [M,K]
              const float* __restrict__ Bt,   // [N,K]
              const float* __restrict__ bias,
              float* __restrict__ C, int do_relu)
{
    extern __shared__ uint32_t smw[];
    uint32_t* Ah = smw;
    uint32_t* Al = Ah + TILEW;
    uint32_t* Bh = Al + TILEW;
    uint32_t* Bl = Bh + TILEW;

    const int tid  = threadIdx.x;
    const int wid  = tid >> 5;
    const int lane = tid & 31;
    const int g    = lane >> 2;      // groupID 0..7
    const int tig  = lane & 3;       // thread-in-group 0..3
    const int warpRow = (wid & 1) * 64;
    const int warpCol = (wid >> 1) * 32;
    const int rowBase = blockIdx.y * 128;
    const int colBase = blockIdx.x * 128;

    float acc[4][4][4];
    #pragma unroll
    for (int mf = 0; mf < 4; mf++)
        #pragma unroll
        for (int nf = 0; nf < 4; nf++)
            #pragma unroll
            for (int r = 0; r < 4; r++) acc[mf][nf][r] = 0.0f;

    // Global->SMEM loader mapping: thread covers row=tid/2, 16 cols
    const int lrow = tid >> 1;
    const int lcol = (tid & 1) * 16;
    const bool aval = (rowBase + lrow) < M;
    const float* Ap = A  + (size_t)(rowBase + lrow) * K + lcol;
    const float* Bp = Bt + (size_t)(colBase + lrow) * K + lcol;
    const int obase = lrow * PAD + lcol;

    for (int kc = 0; kc < K; kc += 32) {
        // ---- load + split into tf32 hi/lo ----
        #pragma unroll
        for (int q = 0; q < 4; q++) {
            float4 va = aval ? *(const float4*)(Ap + kc + q * 4)
                             : make_float4(0.f, 0.f, 0.f, 0.f);
            int o = obase + q * 4;
            uint32_t h0 = f2tf32(va.x), h1 = f2tf32(va.y),
                     h2 = f2tf32(va.z), h3 = f2tf32(va.w);
            Ah[o+0] = h0; Ah[o+1] = h1; Ah[o+2] = h2; Ah[o+3] = h3;
            Al[o+0] = f2tf32(va.x - __uint_as_float(h0));
            Al[o+1] = f2tf32(va.y - __uint_as_float(h1));
            Al[o+2] = f2tf32(va.z - __uint_as_float(h2));
            Al[o+3] = f2tf32(va.w - __uint_as_float(h3));
        }
        #pragma unroll
        for (int q = 0; q < 4; q++) {
            float4 vb = *(const float4*)(Bp + kc + q * 4);
            int o = obase + q * 4;
            uint32_t h0 = f2tf32(vb.x), h1 = f2tf32(vb.y),
                     h2 = f2tf32(vb.z), h3 = f2tf32(vb.w);
            Bh[o+0] = h0; Bh[o+1] = h1; Bh[o+2] = h2; Bh[o+3] = h3;
            Bl[o+0] = f2tf32(vb.x - __uint_as_float(h0));
            Bl[o+1] = f2tf32(vb.y - __uint_as_float(h1));
            Bl[o+2] = f2tf32(vb.z - __uint_as_float(h2));
            Bl[o+3] = f2tf32(vb.w - __uint_as_float(h3));
        }
        __syncthreads();

        // ---- compute: 4 k-steps of 8 ----
        #pragma unroll
        for (int ks = 0; ks < 4; ks++) {
            const int k8 = ks * 8;
            uint32_t ah[4][4], al[4][4];
            #pragma unroll
            for (int mf = 0; mf < 4; mf++) {
                int r0 = (warpRow + mf * 16 + g) * PAD + k8 + tig;
                int r8 = r0 + 8 * PAD;
                ah[mf][0] = Ah[r0];     ah[mf][1] = Ah[r8];
                ah[mf][2] = Ah[r0 + 4]; ah[mf][3] = Ah[r8 + 4];
                al[mf][0] = Al[r0];     al[mf][1] = Al[r8];
                al[mf][2] = Al[r0 + 4]; al[mf][3] = Al[r8 + 4];
            }
            #pragma unroll
            for (int nf = 0; nf < 4; nf++) {
                int nb = (warpCol + nf * 8 + g) * PAD + k8 + tig;
                uint32_t bh0 = Bh[nb], bh1 = Bh[nb + 4];
                uint32_t bl0 = Bl[nb], bl1 = Bl[nb + 4];
                #pragma unroll
                for (int mf = 0; mf < 4; mf++) {
                    mma8(acc[mf][nf], ah[mf], bh0, bh1);
                    mma8(acc[mf][nf], ah[mf], bl0, bl1);
                    mma8(acc[mf][nf], al[mf], bh0, bh1);
                }
            }
        }
        __syncthreads();
    }

    // ---- epilogue ----
    #pragma unroll
    for (int mf = 0; mf < 4; mf++) {
        int r0 = rowBase + warpRow + mf * 16 + g;
        int r1 = r0 + 8;
        #pragma unroll
        for (int nf = 0; nf < 4; nf++) {
            int col = colBase + warpCol + nf * 8 + tig * 2;
            float b0v = 0.f, b1v = 0.f;
            if (bias) { b0v = bias[col]; b1v = bias[col + 1]; }
            float2 v0 = make_float2(acc[mf][nf][0] + b0v, acc[mf][nf][1] + b1v);
            float2 v1 = make_float2(acc[mf][nf][2] + b0v, acc[mf][nf][3] + b1v);
            if (do_relu) {
                v0.x = fmaxf(v0.x, 0.f); v0.y = fmaxf(v0.y, 0.f);
                v1.x = fmaxf(v1.x, 0.f); v1.y = fmaxf(v1.y, 0.f);
            }
            if (r0 < M) *(float2*)&C[(size_t)r0 * N + col] = v0;
            if (r1 < M) *(float2*)&C[(size_t)r1 * N + col] = v1;
        }
    }
}

// ---------------------------------------------------------------------------
// Weight transpose: Wt[N,K] from W[K,N]
// ---------------------------------------------------------------------------
__global__ void transpose_kernel(const float* __restrict__ W,
                                 float* __restrict__ Wt, int K, int N)
{
    __shared__ float t[32][33];
    int kb = blockIdx.y * 32, nb = blockIdx.x * 32;
    int k = kb + threadIdx.y, n = nb + threadIdx.x;
    if (k < K && n < N) t[threadIdx.y][threadIdx.x] = W[(size_t)k * N + n];
    __syncthreads();
    int n2 = nb + threadIdx.y, k2 = kb + threadIdx.x;
    if (n2 < N && k2 < K) Wt[(size_t)n2 * K + k2] = t[threadIdx.x][threadIdx.y];
}

// ---------------------------------------------------------------------------
// Edge pipeline (unchanged, known-correct from round 1)
// ---------------------------------------------------------------------------
__device__ __forceinline__ void atomicMaxFloat(float* addr, float v) {
    if (v >= 0.0f) atomicMax((int*)addr, __float_as_int(v));
    else           atomicMin((unsigned int*)addr, __float_as_uint(v));
}

__device__ __forceinline__ void redAddF4(float* p, float4 r) {
    asm volatile("red.global.add.v4.f32 [%0], {%1,%2,%3,%4};"
                 :: "l"(p), "f"(r.x), "f"(r.y), "f"(r.z), "f"(r.w) : "memory");
}

__global__ void alpha_init_kernel(
    const float* __restrict__ h, const float* __restrict__ a_src,
    const float* __restrict__ a_dst, int Nn, int H, int C,
    float* __restrict__ asrc, float* __restrict__ adst,
    float* __restrict__ emax, float* __restrict__ denom)
{
    int idx  = (blockIdx.x * blockDim.x + threadIdx.x) >> 5;
    int lane = threadIdx.x & 31;
    if (idx >= Nn * H) return;
    int node = idx / H;
    int head = idx % H;

    const float* hp = h + (size_t)node * H * C + head * C;
    const float* as = a_src + head * C;
    const float* ad = a_dst + head * C;
    float s1 = 0.f, s2 = 0.f;
    for (int c = lane; c < C; c += 32) {
        float v = hp[c];
        s1 = fmaf(v, as[c], s1);
        s2 = fmaf(v, ad[c], s2);
    }
    #pragma unroll
    for (int off = 16; off; off >>= 1) {
        s1 += __shfl_xor_sync(0xffffffffu, s1, off);
        s2 += __shfl_xor_sync(0xffffffffu, s2, off);
    }
    if (lane == 0) {
        asrc[idx]  = s1;
        adst[idx]  = s2;
        emax[idx]  = -1e30f;
        denom[idx] = 0.f;
    }
}

__global__ void edge_max_kernel(
    const int* __restrict__ ei, int E, int Nn, int H,
    const float* __restrict__ asrc, const float* __restrict__ adst,
    float* __restrict__ escr, float* __restrict__ emax)
{
    int i = blockIdx.x * blockDim.x + threadIdx.x;
    int tot = E + Nn;
    if (i >= tot) return;
    int s, d; bool valid;
    if (i < E) { s = ei[i]; d = ei[E + i]; valid = (s != d); }
    else       { s = d = i - E; valid = true; }

    for (int h = 0; h < H; h++) {
        float e = -1e30f;
        if (valid) {
            float v = asrc[s * H + h] + adst[d * H + h];
            e = (v > 0.f) ? v : SLOPE * v;
            atomicMaxFloat(&emax[d * H + h], e);
        }
        escr[(size_t)i * H + h] = e;
    }
}

__global__ void edge_denom_kernel(
    const int* __restrict__ ei, int E, int Nn, int H,
    const float* __restrict__ emax,
    float* __restrict__ escr, float* __restrict__ denom)
{
    int i = blockIdx.x * blockDim.x + threadIdx.x;
    int tot = E + Nn;
    if (i >= tot) return;
    int d = (i < E) ? ei[E + i] : (i - E);
    for (int h = 0; h < H; h++) {
        float w = expf(escr[(size_t)i * H + h] - emax[d * H + h]);
        escr[(size_t)i * H + h] = w;
        if (w != 0.f) atomicAdd(&denom[d * H + h], w);
    }
}

__global__ void edge_aggregate_kernel(
    const int* __restrict__ ei, int E, int Nn, int H, int C,
    const float* __restrict__ w_e, const float* __restrict__ denom,
    const float* __restrict__ hfeat, float* __restrict__ out)
{
    int gw   = (blockIdx.x * blockDim.x + threadIdx.x) >> 5;
    int lane = threadIdx.x & 31;
    int tot = E + Nn;
    if (gw >= tot) return;
    int s, d;
    if (gw < E) { s = ei[gw]; d = ei[E + gw]; } else { s = d = gw - E; }

    const int F  = H * C;
    const int Q  = F / 4;
    const float* hs = hfeat + (size_t)s * F;
    float* op = out + (size_t)d * F;

    for (int q = lane; q < Q; q += 32) {
        int col  = q * 4;
        int head = col / C;
        float w = w_e[(size_t)gw * H + head];
        float coef = w / denom[d * H + head];
        float4 hv = *(const float4*)&hs[col];
        float4 r  = make_float4(hv.x * coef, hv.y * coef, hv.z * coef, hv.w * coef);
        redAddF4(&op[col], r);
    }
}

__global__ void bias_relu_kernel(float4* __restrict__ x,
                                 const float* __restrict__ b, int total4)
{
    int i = blockIdx.x * blockDim.x + threadIdx.x;
    if (i >= total4) return;
    int c = (i & 63) * 4;
    float4 v = x[i];
    v.x = fmaxf(v.x + b[c + 0], 0.f);
    v.y = fmaxf(v.y + b[c + 1], 0.f);
    v.z = fmaxf(v.z + b[c + 2], 0.f);
    v.w = fmaxf(v.w + b[c + 3], 0.f);
    x[i] = v;
}

// ---------------------------------------------------------------------------
// Final: out = softmax(relu(X @ lw3 + lb3)), X:[N,1024]
// ---------------------------------------------------------------------------
__global__ __launch_bounds__(128) void final_kernel(
    const float* __restrict__ X, const float* __restrict__ W,
    const float* __restrict__ b, float* __restrict__ out, int K)
{
    int n = blockIdx.x;
    const float* x = X + (size_t)n * K;

    float acc[NCLS];
    #pragma unroll
    for (int c = 0; c < NCLS; c++) acc[c] = 0.f;

    for (int k = threadIdx.x; k < K; k += 128) {
        float xv = x[k];
        const float* wr = W + (size_t)k * NCLS;
        #pragma unroll
        for (int c = 0; c < NCLS; c++) acc[c] = fmaf(xv, wr[c], acc[c]);
    }
    #pragma unroll
    for (int c = 0; c < NCLS; c++)
        #pragma unroll
        for (int off = 16; off; off >>= 1)
            acc[c] += __shfl_xor_sync(0xffffffffu, acc[c], off);

    __shared__ float sm[4][NCLS];
    int warp = threadIdx.x >> 5, lane = threadIdx.x & 31;
    if (lane == 0) {
        #pragma unroll
        for (int c = 0; c < NCLS; c++) sm[warp][c] = acc[c];
    }
    __syncthreads();
    if (threadIdx.x == 0) {
        float logits[NCLS];
        float m = -1e30f;
        #pragma unroll
        for (int c = 0; c < NCLS; c++) {
            float v = sm[0][c] + sm[1][c] + sm[2][c] + sm[3][c] + b[c];
            v = fmaxf(v, 0.f);
            logits[c] = v;
            m = fmaxf(m, v);
        }
        float ssum = 0.f;
        #pragma unroll
        for (int c = 0; c < NCLS; c++) { logits[c] = expf(logits[c] - m); ssum += logits[c]; }
        float inv = 1.f / ssum;
        #pragma unroll
        for (int c = 0; c < NCLS; c++) out[(size_t)n * NCLS + c] = logits[c] * inv;
    }
}

// ---------------------------------------------------------------------------
// Launch
// ---------------------------------------------------------------------------
static inline int ceil_div(int a, int b) { return (a + b - 1) / b; }

extern "C" void kernel_launch(void* const* d_in, const int* in_sizes, int n_in,
                              void* d_out, int out_size)
{
    const float* x      = (const float*)d_in[0];
    const int*   ei     = (const int*)  d_in[1];
    const float* W0     = (const float*)d_in[2];
    const float* a_src0 = (const float*)d_in[3];
    const float* a_dst0 = (const float*)d_in[4];
    const float* b0     = (const float*)d_in[5];
    const float* W1     = (const float*)d_in[6];
    const float* a_src1 = (const float*)d_in[7];
    const float* a_dst1 = (const float*)d_in[8];
    const float* b1     = (const float*)d_in[9];
    const float* lw1    = (const float*)d_in[10];
    const float* lb1    = (const float*)d_in[11];
    const float* lw2    = (const float*)d_in[12];
    const float* lb2    = (const float*)d_in[13];
    const float* lw3    = (const float*)d_in[14];
    const float* lb3    = (const float*)d_in[15];
    float* out = (float*)d_out;

    const int Nn = in_sizes[0] / F_IN;
    const int E  = in_sizes[1] / 2;
    const int tot = E + Nn;

    float *p_h, *p_out, *p_out2, *p_t1, *p_t2;
    float *p_asrc, *p_adst, *p_emax, *p_denom, *p_escr;
    float *p_wt0, *p_wt1, *p_wt2, *p_wt3;
    cudaGetSymbolAddress((void**)&p_h,     g_h);
    cudaGetSymbolAddress((void**)&p_out,   g_out);
    cudaGetSymbolAddress((void**)&p_out2,  g_out2);
    cudaGetSymbolAddress((void**)&p_t1,    g_t1);
    cudaGetSymbolAddress((void**)&p_t2,    g_t2);
    cudaGetSymbolAddress((void**)&p_asrc,  g_asrc);
    cudaGetSymbolAddress((void**)&p_adst,  g_adst);
    cudaGetSymbolAddress((void**)&p_emax,  g_emax);
    cudaGetSymbolAddress((void**)&p_denom, g_denom);
    cudaGetSymbolAddress((void**)&p_escr,  g_escr);
    cudaGetSymbolAddress((void**)&p_wt0,   g_wt0);
    cudaGetSymbolAddress((void**)&p_wt1,   g_wt1);
    cudaGetSymbolAddress((void**)&p_wt2,   g_wt2);
    cudaGetSymbolAddress((void**)&p_wt3,   g_wt3);

    cudaFuncSetAttribute(mma_gemm, cudaFuncAttributeMaxDynamicSharedMemorySize,
                         GEMM_SMEM_BYTES);

    const int gy = ceil_div(Nn, 128);
    dim3 tb(32, 32);

    // Pre-transpose weights to [N,K]
    transpose_kernel<<<dim3(256 / 32, 128 / 32), tb>>>(W0,  p_wt0, 128, 256);
    transpose_kernel<<<dim3(256 / 32, 256 / 32), tb>>>(W1,  p_wt1, 256, 256);
    transpose_kernel<<<dim3(512 / 32, 256 / 32), tb>>>(lw1, p_wt2, 256, 512);
    transpose_kernel<<<dim3(1024 / 32, 512 / 32), tb>>>(lw2, p_wt3, 512, 1024);

    // ---------------- GAT layer 0 ----------------
    mma_gemm<<<dim3(F0 / 128, gy), 256, GEMM_SMEM_BYTES>>>(
        Nn, F0, F_IN, x, p_wt0, nullptr, p_h, 0);
    alpha_init_kernel<<<ceil_div(Nn * H0 * 32, 256), 256>>>(
        p_h, a_src0, a_dst0, Nn, H0, C0, p_asrc, p_adst, p_emax, p_denom);
    edge_max_kernel<<<ceil_div(tot, 256), 256>>>(ei, E, Nn, H0, p_asrc, p_adst, p_escr, p_emax);
    edge_denom_kernel<<<ceil_div(tot, 256), 256>>>(ei, E, Nn, H0, p_emax, p_escr, p_denom);
    cudaMemsetAsync(p_out, 0, (size_t)Nn * F0 * sizeof(float), 0);
    edge_aggregate_kernel<<<ceil_div(tot * 32, 256), 256>>>(
        ei, E, Nn, H0, C0, p_escr, p_denom, p_h, p_out);
    bias_relu_kernel<<<ceil_div(Nn * F0 / 4, 256), 256>>>((float4*)p_out, b0, Nn * F0 / 4);

    // ---------------- GAT layer 1 ----------------
    mma_gemm<<<dim3(F1 / 128, gy), 256, GEMM_SMEM_BYTES>>>(
        Nn, F1, F0, p_out, p_wt1, nullptr, p_h, 0);
    alpha_init_kernel<<<ceil_div(Nn * H1 * 32, 256), 256>>>(
        p_h, a_src1, a_dst1, Nn, H1, C1, p_asrc, p_adst, p_emax, p_denom);
    edge_max_kernel<<<ceil_div(tot, 256), 256>>>(ei, E, Nn, H1, p_asrc, p_adst, p_escr, p_emax);
    edge_denom_kernel<<<ceil_div(tot, 256), 256>>>(ei, E, Nn, H1, p_emax, p_escr, p_denom);
    cudaMemsetAsync(p_out2, 0, (size_t)Nn * F1 * sizeof(float), 0);
    edge_aggregate_kernel<<<ceil_div(tot * 32, 256), 256>>>(
        ei, E, Nn, H1, C1, p_escr, p_denom, p_h, p_out2);
    bias_relu_kernel<<<ceil_div(Nn * F1 / 4, 256), 256>>>((float4*)p_out2, b1, Nn * F1 / 4);

    // ---------------- MLP ----------------
    mma_gemm<<<dim3(512 / 128, gy), 256, GEMM_SMEM_BYTES>>>(
        Nn, 512, 256, p_out2, p_wt2, lb1, p_t1, 1);
    mma_gemm<<<dim3(1024 / 128, gy), 256, GEMM_SMEM_BYTES>>>(
        Nn, 1024, 512, p_t1, p_wt3, lb2, p_t2, 1);
    final_kernel<<<Nn, 128>>>(p_t2, lw3, lb3, out, 1024);
}

// round 5
// speedup vs baseline: 1.3344x; 1.0772x over previous
#include <cuda_runtime.h>
#include <math.h>
#include <stdint.h>

// ---------------------------------------------------------------------------
// Problem constants
// ---------------------------------------------------------------------------
#define NN     50000
#define EE     400000
#define F_IN   128
#define H0     4
#define C0     64
#define F0     (H0*C0)    // 256
#define H1     1
#define C1     256
#define F1     256
#define NCLS   10
#define SLOPE  0.2f

// ---------------------------------------------------------------------------
// Scratch (device globals)
// ---------------------------------------------------------------------------
__device__ float g_h   [NN * 256];
__device__ float g_out [NN * 256];
__device__ float g_out2[NN * 256];
__device__ float g_t1  [NN * 512];
__device__ float g_t2  [NN * 1024];
__device__ float g_asrc[NN * H0];
__device__ float g_adst[NN * H0];
__device__ float g_emax[NN * H0];
__device__ float g_denom[NN * H0];
__device__ float g_escr[(EE + NN) * H0];
// transposed weights [N,K]
__device__ float g_wt0[256 * 128];
__device__ float g_wt1[256 * 256];
__device__ float g_wt2[512 * 256];
__device__ float g_wt3[1024 * 512];

// ---------------------------------------------------------------------------
// helpers (baseline PTX only: sm_80-era mma.sync + cp.async)
// ---------------------------------------------------------------------------
__device__ __forceinline__ uint32_t f2tf32(float x) {
    uint32_t r;
    asm("cvt.rna.tf32.f32 %0, %1;" : "=r"(r) : "f"(x));
    return r;
}

__device__ __forceinline__ void mma8(float c[4], const uint32_t a[4],
                                     uint32_t b0, uint32_t b1) {
    asm volatile(
        "mma.sync.aligned.m16n8k8.row.col.f32.tf32.tf32.f32 "
        "{%0,%1,%2,%3}, {%4,%5,%6,%7}, {%8,%9}, {%0,%1,%2,%3};"
        : "+f"(c[0]), "+f"(c[1]), "+f"(c[2]), "+f"(c[3])
        : "r"(a[0]), "r"(a[1]), "r"(a[2]), "r"(a[3]), "r"(b0), "r"(b1));
}

__device__ __forceinline__ uint32_t smem_u32(const void* p) {
    uint32_t a;
    asm("{ .reg .u64 t; cvta.to.shared.u64 t, %1; cvt.u32.u64 %0, t; }"
        : "=r"(a) : "l"(p));
    return a;
}

__device__ __forceinline__ void cp16(uint32_t dst, const void* src, int srcsize) {
    asm volatile("cp.async.ca.shared.global [%0], [%1], 16, %2;"
                 :: "r"(dst), "l"(src), "r"(srcsize));
}
#define CP_COMMIT() asm volatile("cp.async.commit_group;")
#define CP_WAIT(n)  asm volatile("cp.async.wait_group %0;" :: "n"(n))

// ---------------------------------------------------------------------------
// TF32x3 tensor-core GEMM:  C[M,N] = A[M,K] @ Bt[N,K]^T  (+bias, +relu)
// CTA 128x128, BK=32, 256 threads (8 warps 2x4), warp tile 64x32.
// cp.async double-buffered raw-fp32 staging; hi/lo split in fragment regs.
// 3x compensation: ah*bh + ah*bl + al*bh.
// N % 128 == 0, K % 32 == 0; M guarded.  SMEM rows padded to 36 words.
// ---------------------------------------------------------------------------
#define PAD   36
#define STG_W (128 * PAD)                      // words per operand tile
#define GEMM_SMEM_BYTES (4 * STG_W * 4)        // 2 stages x (A+B) = 73728 B

__global__ __launch_bounds__(256, 2)
void mma_gemm(int M, int N, int K,
              const float* __restrict__ A,    // [M,K]
              const float* __restrict__ Bt,   // [N,K]
              const float* __restrict__ bias,
              float* __restrict__ C, int do_relu)
{
    extern __shared__ float sm[];
    // stage layout: [A0][B0][A1][B1]
    const uint32_t smbase = smem_u32(sm);

    const int tid  = threadIdx.x;
    const int wid  = tid >> 5;
    const int lane = tid & 31;
    const int g    = lane >> 2;
    const int tig  = lane & 3;
    const int warpRow = (wid & 1) * 64;
    const int warpCol = (wid >> 1) * 32;
    const int rowBase = blockIdx.y * 128;
    const int colBase = blockIdx.x * 128;

    float acc[4][4][4];
    #pragma unroll
    for (int mf = 0; mf < 4; mf++)
        #pragma unroll
        for (int nf = 0; nf < 4; nf++)
            #pragma unroll
            for (int r = 0; r < 4; r++) acc[mf][nf][r] = 0.0f;

    // loader: thread covers row = tid/2, 16 cols starting at (tid&1)*16
    const int lrow = tid >> 1;
    const int lcol = (tid & 1) * 16;
    const int asz  = ((rowBase + lrow) < M) ? 16 : 0;
    const float* Ap = A  + (size_t)(rowBase + lrow) * K + lcol;
    const float* Bp = Bt + (size_t)(colBase + lrow) * K + lcol;
    const uint32_t toff = (uint32_t)(lrow * PAD + lcol) * 4;  // byte off in tile

    const int nch = K / 32;

    // prologue: stage 0
    {
        uint32_t ab = smbase + toff;
        uint32_t bb = smbase + STG_W * 4 + toff;
        #pragma unroll
        for (int q = 0; q < 4; q++) {
            cp16(ab + q * 16, Ap + q * 4, asz);
            cp16(bb + q * 16, Bp + q * 4, 16);
        }
        CP_COMMIT();
    }

    for (int kc = 0; kc < nch; kc++) {
        if (kc + 1 < nch) {
            const int s = (kc + 1) & 1;
            uint32_t ab = smbase + (uint32_t)(2 * s) * STG_W * 4 + toff;
            uint32_t bb = smbase + (uint32_t)(2 * s + 1) * STG_W * 4 + toff;
            const int kb = (kc + 1) * 32;
            #pragma unroll
            for (int q = 0; q < 4; q++) {
                cp16(ab + q * 16, Ap + kb + q * 4, asz);
                cp16(bb + q * 16, Bp + kb + q * 4, 16);
            }
            CP_COMMIT();
            CP_WAIT(1);
        } else {
            CP_WAIT(0);
        }
        __syncthreads();

        const float* Acur = sm + (size_t)(2 * (kc & 1)) * STG_W;
        const float* Bcur = Acur + STG_W;

        #pragma unroll
        for (int ks = 0; ks < 4; ks++) {
            const int k8 = ks * 8;
            uint32_t ah[4][4], al[4][4];
            #pragma unroll
            for (int mf = 0; mf < 4; mf++) {
                int r0 = (warpRow + mf * 16 + g) * PAD + k8 + tig;
                int r8 = r0 + 8 * PAD;
                float v0 = Acur[r0],     v1 = Acur[r8];
                float v2 = Acur[r0 + 4], v3 = Acur[r8 + 4];
                ah[mf][0] = f2tf32(v0); al[mf][0] = f2tf32(v0 - __uint_as_float(ah[mf][0]));
                ah[mf][1] = f2tf32(v1); al[mf][1] = f2tf32(v1 - __uint_as_float(ah[mf][1]));
                ah[mf][2] = f2tf32(v2); al[mf][2] = f2tf32(v2 - __uint_as_float(ah[mf][2]));
                ah[mf][3] = f2tf32(v3); al[mf][3] = f2tf32(v3 - __uint_as_float(ah[mf][3]));
            }
            #pragma unroll
            for (int nf = 0; nf < 4; nf++) {
                int nb = (warpCol + nf * 8 + g) * PAD + k8 + tig;
                float w0 = Bcur[nb], w1 = Bcur[nb + 4];
                uint32_t bh0 = f2tf32(w0), bh1 = f2tf32(w1);
                uint32_t bl0 = f2tf32(w0 - __uint_as_float(bh0));
                uint32_t bl1 = f2tf32(w1 - __uint_as_float(bh1));
                #pragma unroll
                for (int mf = 0; mf < 4; mf++) {
                    mma8(acc[mf][nf], ah[mf], bh0, bh1);
                    mma8(acc[mf][nf], ah[mf], bl0, bl1);
                    mma8(acc[mf][nf], al[mf], bh0, bh1);
                }
            }
        }
        __syncthreads();
    }

    // ---- epilogue ----
    #pragma unroll
    for (int mf = 0; mf < 4; mf++) {
        int r0 = rowBase + warpRow + mf * 16 + g;
        int r1 = r0 + 8;
        #pragma unroll
        for (int nf = 0; nf < 4; nf++) {
            int col = colBase + warpCol + nf * 8 + tig * 2;
            float b0v = 0.f, b1v = 0.f;
            if (bias) { b0v = bias[col]; b1v = bias[col + 1]; }
            float2 v0 = make_float2(acc[mf][nf][0] + b0v, acc[mf][nf][1] + b1v);
            float2 v1 = make_float2(acc[mf][nf][2] + b0v, acc[mf][nf][3] + b1v);
            if (do_relu) {
                v0.x = fmaxf(v0.x, 0.f); v0.y = fmaxf(v0.y, 0.f);
                v1.x = fmaxf(v1.x, 0.f); v1.y = fmaxf(v1.y, 0.f);
            }
            if (r0 < M) *(float2*)&C[(size_t)r0 * N + col] = v0;
            if (r1 < M) *(float2*)&C[(size_t)r1 * N + col] = v1;
        }
    }
}

// ---------------------------------------------------------------------------
// Weight transpose: Wt[N,K] from W[K,N]
// ---------------------------------------------------------------------------
__global__ void transpose_kernel(const float* __restrict__ W,
                                 float* __restrict__ Wt, int K, int N)
{
    __shared__ float t[32][33];
    int kb = blockIdx.y * 32, nb = blockIdx.x * 32;
    int k = kb + threadIdx.y, n = nb + threadIdx.x;
    if (k < K && n < N) t[threadIdx.y][threadIdx.x] = W[(size_t)k * N + n];
    __syncthreads();
    int n2 = nb + threadIdx.y, k2 = kb + threadIdx.x;
    if (n2 < N && k2 < K) Wt[(size_t)n2 * K + k2] = t[threadIdx.x][threadIdx.y];
}

// ---------------------------------------------------------------------------
// Edge pipeline
// ---------------------------------------------------------------------------
__device__ __forceinline__ void atomicMaxFloat(float* addr, float v) {
    if (v >= 0.0f) atomicMax((int*)addr, __float_as_int(v));
    else           atomicMin((unsigned int*)addr, __float_as_uint(v));
}

__device__ __forceinline__ void redAddF4(float* p, float4 r) {
    asm volatile("red.global.add.v4.f32 [%0], {%1,%2,%3,%4};"
                 :: "l"(p), "f"(r.x), "f"(r.y), "f"(r.z), "f"(r.w) : "memory");
}

__global__ void alpha_init_kernel(
    const float* __restrict__ h, const float* __restrict__ a_src,
    const float* __restrict__ a_dst, int Nn, int H, int C,
    float* __restrict__ asrc, float* __restrict__ adst,
    float* __restrict__ emax, float* __restrict__ denom)
{
    int idx  = (blockIdx.x * blockDim.x + threadIdx.x) >> 5;
    int lane = threadIdx.x & 31;
    if (idx >= Nn * H) return;
    int node = idx / H;
    int head = idx % H;

    const float* hp = h + (size_t)node * H * C + head * C;
    const float* as = a_src + head * C;
    const float* ad = a_dst + head * C;
    float s1 = 0.f, s2 = 0.f;
    for (int c = lane; c < C; c += 32) {
        float v = hp[c];
        s1 = fmaf(v, as[c], s1);
        s2 = fmaf(v, ad[c], s2);
    }
    #pragma unroll
    for (int off = 16; off; off >>= 1) {
        s1 += __shfl_xor_sync(0xffffffffu, s1, off);
        s2 += __shfl_xor_sync(0xffffffffu, s2, off);
    }
    if (lane == 0) {
        asrc[idx]  = s1;
        adst[idx]  = s2;
        emax[idx]  = -1e30f;
        denom[idx] = 0.f;
    }
}

__global__ void edge_max_kernel(
    const int* __restrict__ ei, int E, int Nn, int H,
    const float* __restrict__ asrc, const float* __restrict__ adst,
    float* __restrict__ escr, float* __restrict__ emax)
{
    int i = blockIdx.x * blockDim.x + threadIdx.x;
    int tot = E + Nn;
    if (i >= tot) return;
    int s, d; bool valid;
    if (i < E) { s = ei[i]; d = ei[E + i]; valid = (s != d); }
    else       { s = d = i - E; valid = true; }

    for (int h = 0; h < H; h++) {
        float e = -1e30f;
        if (valid) {
            float v = asrc[s * H + h] + adst[d * H + h];
            e = (v > 0.f) ? v : SLOPE * v;
            atomicMaxFloat(&emax[d * H + h], e);
        }
        escr[(size_t)i * H + h] = e;
    }
}

__global__ void edge_denom_kernel(
    const int* __restrict__ ei, int E, int Nn, int H,
    const float* __restrict__ emax,
    float* __restrict__ escr, float* __restrict__ denom)
{
    int i = blockIdx.x * blockDim.x + threadIdx.x;
    int tot = E + Nn;
    if (i >= tot) return;
    int d = (i < E) ? ei[E + i] : (i - E);
    for (int h = 0; h < H; h++) {
        float w = expf(escr[(size_t)i * H + h] - emax[d * H + h]);
        escr[(size_t)i * H + h] = w;
        if (w != 0.f) atomicAdd(&denom[d * H + h], w);
    }
}

// Pass 3: out[dst] += (w/denom[dst]) * h[src]. Warp per edge.
// Normalization coef computed ONCE per (edge,head) in lanes 0..H-1,
// broadcast to the feature loop via shfl (kills 64 divisions+gathers/edge).
__global__ void edge_aggregate_kernel(
    const int* __restrict__ ei, int E, int Nn, int H, int cshift,  // C = 1<<cshift
    const float* __restrict__ w_e, const float* __restrict__ denom,
    const float* __restrict__ hfeat, float* __restrict__ out)
{
    int gw   = (blockIdx.x * blockDim.x + threadIdx.x) >> 5;
    int lane = threadIdx.x & 31;
    int tot = E + Nn;
    if (gw >= tot) return;
    int s, d;
    if (gw < E) { s = ei[gw]; d = ei[E + gw]; } else { s = d = gw - E; }

    float coef_l = 0.f;
    if (lane < H)
        coef_l = w_e[(size_t)gw * H + lane] / denom[d * H + lane];

    const int F = H << cshift;
    const int Q = F / 4;
    const float* hs = hfeat + (size_t)s * F;
    float* op = out + (size_t)d * F;

    for (int q = lane; q < Q; q += 32) {
        int col  = q << 2;
        int head = col >> cshift;
        float coef = __shfl_sync(0xffffffffu, coef_l, head);
        float4 hv = *(const float4*)&hs[col];
        redAddF4(&op[col], make_float4(hv.x * coef, hv.y * coef,
                                       hv.z * coef, hv.w * coef));
    }
}

__global__ void bias_relu_kernel(float4* __restrict__ x,
                                 const float* __restrict__ b, int total4)
{
    int i = blockIdx.x * blockDim.x + threadIdx.x;
    if (i >= total4) return;
    int c = (i & 63) * 4;
    float4 v = x[i];
    v.x = fmaxf(v.x + b[c + 0], 0.f);
    v.y = fmaxf(v.y + b[c + 1], 0.f);
    v.z = fmaxf(v.z + b[c + 2], 0.f);
    v.w = fmaxf(v.w + b[c + 3], 0.f);
    x[i] = v;
}

// ---------------------------------------------------------------------------
// Final: out = softmax(relu(X @ lw3 + lb3)), X:[N,1024]
// ---------------------------------------------------------------------------
__global__ __launch_bounds__(128) void final_kernel(
    const float* __restrict__ X, const float* __restrict__ W,
    const float* __restrict__ b, float* __restrict__ out, int K)
{
    int n = blockIdx.x;
    const float* x = X + (size_t)n * K;

    float acc[NCLS];
    #pragma unroll
    for (int c = 0; c < NCLS; c++) acc[c] = 0.f;

    for (int k = threadIdx.x; k < K; k += 128) {
        float xv = x[k];
        const float* wr = W + (size_t)k * NCLS;
        #pragma unroll
        for (int c = 0; c < NCLS; c++) acc[c] = fmaf(xv, wr[c], acc[c]);
    }
    #pragma unroll
    for (int c = 0; c < NCLS; c++)
        #pragma unroll
        for (int off = 16; off; off >>= 1)
            acc[c] += __shfl_xor_sync(0xffffffffu, acc[c], off);

    __shared__ float sm[4][NCLS];
    int warp = threadIdx.x >> 5, lane = threadIdx.x & 31;
    if (lane == 0) {
        #pragma unroll
        for (int c = 0; c < NCLS; c++) sm[warp][c] = acc[c];
    }
    __syncthreads();
    if (threadIdx.x == 0) {
        float logits[NCLS];
        float m = -1e30f;
        #pragma unroll
        for (int c = 0; c < NCLS; c++) {
            float v = sm[0][c] + sm[1][c] + sm[2][c] + sm[3][c] + b[c];
            v = fmaxf(v, 0.f);
            logits[c] = v;
            m = fmaxf(m, v);
        }
        float ssum = 0.f;
        #pragma unroll
        for (int c = 0; c < NCLS; c++) { logits[c] = expf(logits[c] - m); ssum += logits[c]; }
        float inv = 1.f / ssum;
        #pragma unroll
        for (int c = 0; c < NCLS; c++) out[(size_t)n * NCLS + c] = logits[c] * inv;
    }
}

// ---------------------------------------------------------------------------
// Launch
// ---------------------------------------------------------------------------
static inline int ceil_div(int a, int b) { return (a + b - 1) / b; }

extern "C" void kernel_launch(void* const* d_in, const int* in_sizes, int n_in,
                              void* d_out, int out_size)
{
    const float* x      = (const float*)d_in[0];
    const int*   ei     = (const int*)  d_in[1];
    const float* W0     = (const float*)d_in[2];
    const float* a_src0 = (const float*)d_in[3];
    const float* a_dst0 = (const float*)d_in[4];
    const float* b0     = (const float*)d_in[5];
    const float* W1     = (const float*)d_in[6];
    const float* a_src1 = (const float*)d_in[7];
    const float* a_dst1 = (const float*)d_in[8];
    const float* b1     = (const float*)d_in[9];
    const float* lw1    = (const float*)d_in[10];
    const float* lb1    = (const float*)d_in[11];
    const float* lw2    = (const float*)d_in[12];
    const float* lb2    = (const float*)d_in[13];
    const float* lw3    = (const float*)d_in[14];
    const float* lb3    = (const float*)d_in[15];
    float* out = (float*)d_out;

    const int Nn = in_sizes[0] / F_IN;
    const int E  = in_sizes[1] / 2;
    const int tot = E + Nn;

    float *p_h, *p_out, *p_out2, *p_t1, *p_t2;
    float *p_asrc, *p_adst, *p_emax, *p_denom, *p_escr;
    float *p_wt0, *p_wt1, *p_wt2, *p_wt3;
    cudaGetSymbolAddress((void**)&p_h,     g_h);
    cudaGetSymbolAddress((void**)&p_out,   g_out);
    cudaGetSymbolAddress((void**)&p_out2,  g_out2);
    cudaGetSymbolAddress((void**)&p_t1,    g_t1);
    cudaGetSymbolAddress((void**)&p_t2,    g_t2);
    cudaGetSymbolAddress((void**)&p_asrc,  g_asrc);
    cudaGetSymbolAddress((void**)&p_adst,  g_adst);
    cudaGetSymbolAddress((void**)&p_emax,  g_emax);
    cudaGetSymbolAddress((void**)&p_denom, g_denom);
    cudaGetSymbolAddress((void**)&p_escr,  g_escr);
    cudaGetSymbolAddress((void**)&p_wt0,   g_wt0);
    cudaGetSymbolAddress((void**)&p_wt1,   g_wt1);
    cudaGetSymbolAddress((void**)&p_wt2,   g_wt2);
    cudaGetSymbolAddress((void**)&p_wt3,   g_wt3);

    cudaFuncSetAttribute(mma_gemm, cudaFuncAttributeMaxDynamicSharedMemorySize,
                         GEMM_SMEM_BYTES);

    const int gy = ceil_div(Nn, 128);
    dim3 tb(32, 32);

    // Pre-transpose weights to [N,K]
    transpose_kernel<<<dim3(256 / 32, 128 / 32), tb>>>(W0,  p_wt0, 128, 256);
    transpose_kernel<<<dim3(256 / 32, 256 / 32), tb>>>(W1,  p_wt1, 256, 256);
    transpose_kernel<<<dim3(512 / 32, 256 / 32), tb>>>(lw1, p_wt2, 256, 512);
    transpose_kernel<<<dim3(1024 / 32, 512 / 32), tb>>>(lw2, p_wt3, 512, 1024);

    // ---------------- GAT layer 0 ----------------
    mma_gemm<<<dim3(F0 / 128, gy), 256, GEMM_SMEM_BYTES>>>(
        Nn, F0, F_IN, x, p_wt0, nullptr, p_h, 0);
    alpha_init_kernel<<<ceil_div(Nn * H0 * 32, 256), 256>>>(
        p_h, a_src0, a_dst0, Nn, H0, C0, p_asrc, p_adst, p_emax, p_denom);
    edge_max_kernel<<<ceil_div(tot, 256), 256>>>(ei, E, Nn, H0, p_asrc, p_adst, p_escr, p_emax);
    edge_denom_kernel<<<ceil_div(tot, 256), 256>>>(ei, E, Nn, H0, p_emax, p_escr, p_denom);
    cudaMemsetAsync(p_out, 0, (size_t)Nn * F0 * sizeof(float), 0);
    edge_aggregate_kernel<<<ceil_div(tot * 32, 256), 256>>>(
        ei, E, Nn, H0, 6, p_escr, p_denom, p_h, p_out);
    bias_relu_kernel<<<ceil_div(Nn * F0 / 4, 256), 256>>>((float4*)p_out, b0, Nn * F0 / 4);

    // ---------------- GAT layer 1 ----------------
    mma_gemm<<<dim3(F1 / 128, gy), 256, GEMM_SMEM_BYTES>>>(
        Nn, F1, F0, p_out, p_wt1, nullptr, p_h, 0);
    alpha_init_kernel<<<ceil_div(Nn * H1 * 32, 256), 256>>>(
        p_h, a_src1, a_dst1, Nn, H1, C1, p_asrc, p_adst, p_emax, p_denom);
    edge_max_kernel<<<ceil_div(tot, 256), 256>>>(ei, E, Nn, H1, p_asrc, p_adst, p_escr, p_emax);
    edge_denom_kernel<<<ceil_div(tot, 256), 256>>>(ei, E, Nn, H1, p_emax, p_escr, p_denom);
    cudaMemsetAsync(p_out2, 0, (size_t)Nn * F1 * sizeof(float), 0);
    edge_aggregate_kernel<<<ceil_div(tot * 32, 256), 256>>>(
        ei, E, Nn, H1, 8, p_escr, p_denom, p_h, p_out2);
    bias_relu_kernel<<<ceil_div(Nn * F1 / 4, 256), 256>>>((float4*)p_out2, b1, Nn * F1 / 4);

    // ---------------- MLP ----------------
    mma_gemm<<<dim3(512 / 128, gy), 256, GEMM_SMEM_BYTES>>>(
        Nn, 512, 256, p_out2, p_wt2, lb1, p_t1, 1);
    mma_gemm<<<dim3(1024 / 128, gy), 256, GEMM_SMEM_BYTES>>>(
        Nn, 1024, 512, p_t1, p_wt3, lb2, p_t2, 1);
    final_kernel<<<Nn, 128>>>(p_t2, lw3, lb3, out, 1024);
}

// round 6
// speedup vs baseline: 1.5223x; 1.1408x over previous
#include <cuda_runtime.h>
#include <math.h>
#include <stdint.h>

// ---------------------------------------------------------------------------
// Problem constants
// ---------------------------------------------------------------------------
#define NN     50000
#define EE     400000
#define F_IN   128
#define H0     4
#define C0     64
#define F0     (H0*C0)    // 256
#define H1     1
#define C1     256
#define F1     256
#define NCLS   10
#define SLOPE  0.2f

// ---------------------------------------------------------------------------
// Scratch (device globals)
// ---------------------------------------------------------------------------
__device__ float g_h   [NN * 256];
__device__ float g_out [NN * 256];
__device__ float g_out2[NN * 256];
__device__ float g_t1  [NN * 512];
__device__ float g_t2  [NN * 1024];
__device__ float g_asrc[NN * H0];
__device__ float g_adst[NN * H0];
__device__ float g_emax[NN * H0];
__device__ float g_denom[NN * H0];
__device__ float g_escr[(EE + NN) * H0];
// transposed weights [N,K]
__device__ float g_wt0[256 * 128];
__device__ float g_wt1[256 * 256];
__device__ float g_wt2[512 * 256];
__device__ float g_wt3[1024 * 512];

// ---------------------------------------------------------------------------
// helpers (baseline PTX: sm_80-era mma.sync bf16 + cp.async)
// ---------------------------------------------------------------------------
__device__ __forceinline__ uint32_t pack_bf16(float hi, float lo) {
    uint32_t r;
    asm("cvt.rn.bf16x2.f32 %0, %1, %2;" : "=r"(r) : "f"(hi), "f"(lo));
    return r;
}

// split float2 (p.x = k even, p.y = k odd) into bf16x2 hi + bf16x2 residual
__device__ __forceinline__ void split2(float2 p, uint32_t& h, uint32_t& l) {
    h = pack_bf16(p.y, p.x);
    float rhi = p.y - __uint_as_float(h & 0xFFFF0000u);
    float rlo = p.x - __uint_as_float(h << 16);
    l = pack_bf16(rhi, rlo);
}

__device__ __forceinline__ void mma16(float c[4], const uint32_t a[4],
                                      uint32_t b0, uint32_t b1) {
    asm volatile(
        "mma.sync.aligned.m16n8k16.row.col.f32.bf16.bf16.f32 "
        "{%0,%1,%2,%3}, {%4,%5,%6,%7}, {%8,%9}, {%0,%1,%2,%3};"
        : "+f"(c[0]), "+f"(c[1]), "+f"(c[2]), "+f"(c[3])
        : "r"(a[0]), "r"(a[1]), "r"(a[2]), "r"(a[3]), "r"(b0), "r"(b1));
}

__device__ __forceinline__ uint32_t smem_u32(const void* p) {
    uint32_t a;
    asm("{ .reg .u64 t; cvta.to.shared.u64 t, %1; cvt.u32.u64 %0, t; }"
        : "=r"(a) : "l"(p));
    return a;
}

__device__ __forceinline__ void cp16(uint32_t dst, const void* src, int srcsize) {
    asm volatile("cp.async.ca.shared.global [%0], [%1], 16, %2;"
                 :: "r"(dst), "l"(src), "r"(srcsize));
}
#define CP_COMMIT() asm volatile("cp.async.commit_group;")
#define CP_WAIT(n)  asm volatile("cp.async.wait_group %0;" :: "n"(n))

// ---------------------------------------------------------------------------
// BF16x3 tensor-core GEMM:  C[M,N] = A[M,K] @ Bt[N,K]^T  (+bias, +relu)
// CTA 128x128, BK=32, 256 threads (8 warps 2x4), warp tile 64x32.
// cp.async double-buffered raw-fp32 staging; bf16 hi/lo split in registers.
// products: ah*bh + ah*bl + al*bh   (rel err ~3e-5, fp32 accum).
// mma.m16n8k16 -> HALF the HMMA count of the tf32x3/m16n8k8 version.
// N % 128 == 0, K % 32 == 0; M guarded.  SMEM rows padded to 36 words.
// ---------------------------------------------------------------------------
#define PAD   36
#define STG_W (128 * PAD)                      // words per operand tile
#define GEMM_SMEM_BYTES (4 * STG_W * 4)        // 2 stages x (A+B) = 73728 B

__global__ __launch_bounds__(256, 2)
void mma_gemm(int M, int N, int K,
              const float* __restrict__ A,    // [M,K]
              const float* __restrict__ Bt,   // [N,K]
              const float* __restrict__ bias,
              float* __restrict__ C, int do_relu)
{
    extern __shared__ float sm[];
    const uint32_t smbase = smem_u32(sm);

    const int tid  = threadIdx.x;
    const int wid  = tid >> 5;
    const int lane = tid & 31;
    const int g    = lane >> 2;
    const int tig  = lane & 3;
    const int warpRow = (wid & 1) * 64;
    const int warpCol = (wid >> 1) * 32;
    const int rowBase = blockIdx.y * 128;
    const int colBase = blockIdx.x * 128;

    float acc[4][4][4];
    #pragma unroll
    for (int mf = 0; mf < 4; mf++)
        #pragma unroll
        for (int nf = 0; nf < 4; nf++)
            #pragma unroll
            for (int r = 0; r < 4; r++) acc[mf][nf][r] = 0.0f;

    // loader: thread covers row = tid/2, 16 cols starting at (tid&1)*16
    const int lrow = tid >> 1;
    const int lcol = (tid & 1) * 16;
    const int asz  = ((rowBase + lrow) < M) ? 16 : 0;
    const float* Ap = A  + (size_t)(rowBase + lrow) * K + lcol;
    const float* Bp = Bt + (size_t)(colBase + lrow) * K + lcol;
    const uint32_t toff = (uint32_t)(lrow * PAD + lcol) * 4;

    const int nch = K / 32;

    // prologue: stage 0
    {
        uint32_t ab = smbase + toff;
        uint32_t bb = smbase + STG_W * 4 + toff;
        #pragma unroll
        for (int q = 0; q < 4; q++) {
            cp16(ab + q * 16, Ap + q * 4, asz);
            cp16(bb + q * 16, Bp + q * 4, 16);
        }
        CP_COMMIT();
    }

    for (int kc = 0; kc < nch; kc++) {
        if (kc + 1 < nch) {
            const int s = (kc + 1) & 1;
            uint32_t ab = smbase + (uint32_t)(2 * s) * STG_W * 4 + toff;
            uint32_t bb = smbase + (uint32_t)(2 * s + 1) * STG_W * 4 + toff;
            const int kb = (kc + 1) * 32;
            #pragma unroll
            for (int q = 0; q < 4; q++) {
                cp16(ab + q * 16, Ap + kb + q * 4, asz);
                cp16(bb + q * 16, Bp + kb + q * 4, 16);
            }
            CP_COMMIT();
            CP_WAIT(1);
        } else {
            CP_WAIT(0);
        }
        __syncthreads();

        const float* Acur = sm + (size_t)(2 * (kc & 1)) * STG_W;
        const float* Bcur = Acur + STG_W;

        // two K=16 steps per BK=32 chunk
        #pragma unroll
        for (int ks = 0; ks < 2; ks++) {
            const int kb = ks * 16 + 2 * tig;
            uint32_t ah[4][4], al[4][4];
            #pragma unroll
            for (int mf = 0; mf < 4; mf++) {
                int r0 = (warpRow + mf * 16 + g) * PAD + kb;
                int r8 = r0 + 8 * PAD;
                split2(*(const float2*)&Acur[r0],     ah[mf][0], al[mf][0]);
                split2(*(const float2*)&Acur[r8],     ah[mf][1], al[mf][1]);
                split2(*(const float2*)&Acur[r0 + 8], ah[mf][2], al[mf][2]);
                split2(*(const float2*)&Acur[r8 + 8], ah[mf][3], al[mf][3]);
            }
            #pragma unroll
            for (int nf = 0; nf < 4; nf++) {
                int nb = (warpCol + nf * 8 + g) * PAD + kb;
                uint32_t bh0, bl0, bh1, bl1;
                split2(*(const float2*)&Bcur[nb],     bh0, bl0);
                split2(*(const float2*)&Bcur[nb + 8], bh1, bl1);
                #pragma unroll
                for (int mf = 0; mf < 4; mf++) {
                    mma16(acc[mf][nf], ah[mf], bh0, bh1);
                    mma16(acc[mf][nf], ah[mf], bl0, bl1);
                    mma16(acc[mf][nf], al[mf], bh0, bh1);
                }
            }
        }
        __syncthreads();
    }

    // ---- epilogue ----
    #pragma unroll
    for (int mf = 0; mf < 4; mf++) {
        int r0 = rowBase + warpRow + mf * 16 + g;
        int r1 = r0 + 8;
        #pragma unroll
        for (int nf = 0; nf < 4; nf++) {
            int col = colBase + warpCol + nf * 8 + tig * 2;
            float b0v = 0.f, b1v = 0.f;
            if (bias) { b0v = bias[col]; b1v = bias[col + 1]; }
            float2 v0 = make_float2(acc[mf][nf][0] + b0v, acc[mf][nf][1] + b1v);
            float2 v1 = make_float2(acc[mf][nf][2] + b0v, acc[mf][nf][3] + b1v);
            if (do_relu) {
                v0.x = fmaxf(v0.x, 0.f); v0.y = fmaxf(v0.y, 0.f);
                v1.x = fmaxf(v1.x, 0.f); v1.y = fmaxf(v1.y, 0.f);
            }
            if (r0 < M) *(float2*)&C[(size_t)r0 * N + col] = v0;
            if (r1 < M) *(float2*)&C[(size_t)r1 * N + col] = v1;
        }
    }
}

// ---------------------------------------------------------------------------
// Weight transpose: Wt[N,K] from W[K,N]
// ---------------------------------------------------------------------------
__global__ void transpose_kernel(const float* __restrict__ W,
                                 float* __restrict__ Wt, int K, int N)
{
    __shared__ float t[32][33];
    int kb = blockIdx.y * 32, nb = blockIdx.x * 32;
    int k = kb + threadIdx.y, n = nb + threadIdx.x;
    if (k < K && n < N) t[threadIdx.y][threadIdx.x] = W[(size_t)k * N + n];
    __syncthreads();
    int n2 = nb + threadIdx.y, k2 = kb + threadIdx.x;
    if (n2 < N && k2 < K) Wt[(size_t)n2 * K + k2] = t[threadIdx.x][threadIdx.y];
}

// ---------------------------------------------------------------------------
// Edge pipeline
// ---------------------------------------------------------------------------
__device__ __forceinline__ void atomicMaxFloat(float* addr, float v) {
    if (v >= 0.0f) atomicMax((int*)addr, __float_as_int(v));
    else           atomicMin((unsigned int*)addr, __float_as_uint(v));
}

__device__ __forceinline__ void redAddF4(float* p, float4 r) {
    asm volatile("red.global.add.v4.f32 [%0], {%1,%2,%3,%4};"
                 :: "l"(p), "f"(r.x), "f"(r.y), "f"(r.z), "f"(r.w) : "memory");
}

__global__ void alpha_init_kernel(
    const float* __restrict__ h, const float* __restrict__ a_src,
    const float* __restrict__ a_dst, int Nn, int H, int C,
    float* __restrict__ asrc, float* __restrict__ adst,
    float* __restrict__ emax, float* __restrict__ denom)
{
    int idx  = (blockIdx.x * blockDim.x + threadIdx.x) >> 5;
    int lane = threadIdx.x & 31;
    if (idx >= Nn * H) return;
    int node = idx / H;
    int head = idx % H;

    const float* hp = h + (size_t)node * H * C + head * C;
    const float* as = a_src + head * C;
    const float* ad = a_dst + head * C;
    float s1 = 0.f, s2 = 0.f;
    for (int c = lane; c < C; c += 32) {
        float v = hp[c];
        s1 = fmaf(v, as[c], s1);
        s2 = fmaf(v, ad[c], s2);
    }
    #pragma unroll
    for (int off = 16; off; off >>= 1) {
        s1 += __shfl_xor_sync(0xffffffffu, s1, off);
        s2 += __shfl_xor_sync(0xffffffffu, s2, off);
    }
    if (lane == 0) {
        asrc[idx]  = s1;
        adst[idx]  = s2;
        emax[idx]  = -1e30f;
        denom[idx] = 0.f;
    }
}

__global__ void edge_max_kernel(
    const int* __restrict__ ei, int E, int Nn, int H,
    const float* __restrict__ asrc, const float* __restrict__ adst,
    float* __restrict__ escr, float* __restrict__ emax)
{
    int i = blockIdx.x * blockDim.x + threadIdx.x;
    int tot = E + Nn;
    if (i >= tot) return;
    int s, d; bool valid;
    if (i < E) { s = ei[i]; d = ei[E + i]; valid = (s != d); }
    else       { s = d = i - E; valid = true; }

    for (int h = 0; h < H; h++) {
        float e = -1e30f;
        if (valid) {
            float v = asrc[s * H + h] + adst[d * H + h];
            e = (v > 0.f) ? v : SLOPE * v;
            atomicMaxFloat(&emax[d * H + h], e);
        }
        escr[(size_t)i * H + h] = e;
    }
}

__global__ void edge_denom_kernel(
    const int* __restrict__ ei, int E, int Nn, int H,
    const float* __restrict__ emax,
    float* __restrict__ escr, float* __restrict__ denom)
{
    int i = blockIdx.x * blockDim.x + threadIdx.x;
    int tot = E + Nn;
    if (i >= tot) return;
    int d = (i < E) ? ei[E + i] : (i - E);
    for (int h = 0; h < H; h++) {
        float w = expf(escr[(size_t)i * H + h] - emax[d * H + h]);
        escr[(size_t)i * H + h] = w;
        if (w != 0.f) atomicAdd(&denom[d * H + h], w);
    }
}

// Pass 3: out[dst] += (w/denom[dst]) * h[src]. Warp per edge; coef hoisted
// to lanes 0..H-1 once and broadcast via shfl.
__global__ void edge_aggregate_kernel(
    const int* __restrict__ ei, int E, int Nn, int H, int cshift,  // C = 1<<cshift
    const float* __restrict__ w_e, const float* __restrict__ denom,
    const float* __restrict__ hfeat, float* __restrict__ out)
{
    int gw   = (blockIdx.x * blockDim.x + threadIdx.x) >> 5;
    int lane = threadIdx.x & 31;
    int tot = E + Nn;
    if (gw >= tot) return;
    int s, d;
    if (gw < E) { s = ei[gw]; d = ei[E + gw]; } else { s = d = gw - E; }

    float coef_l = 0.f;
    if (lane < H)
        coef_l = w_e[(size_t)gw * H + lane] / denom[d * H + lane];

    const int F = H << cshift;
    const int Q = F / 4;
    const float* hs = hfeat + (size_t)s * F;
    float* op = out + (size_t)d * F;

    for (int q = lane; q < Q; q += 32) {
        int col  = q << 2;
        int head = col >> cshift;
        float coef = __shfl_sync(0xffffffffu, coef_l, head);
        float4 hv = *(const float4*)&hs[col];
        redAddF4(&op[col], make_float4(hv.x * coef, hv.y * coef,
                                       hv.z * coef, hv.w * coef));
    }
}

__global__ void bias_relu_kernel(float4* __restrict__ x,
                                 const float* __restrict__ b, int total4)
{
    int i = blockIdx.x * blockDim.x + threadIdx.x;
    if (i >= total4) return;
    int c = (i & 63) * 4;
    float4 v = x[i];
    v.x = fmaxf(v.x + b[c + 0], 0.f);
    v.y = fmaxf(v.y + b[c + 1], 0.f);
    v.z = fmaxf(v.z + b[c + 2], 0.f);
    v.w = fmaxf(v.w + b[c + 3], 0.f);
    x[i] = v;
}

// ---------------------------------------------------------------------------
// Final: out = softmax(relu(X @ lw3 + lb3)), X:[N,1024]
// ---------------------------------------------------------------------------
__global__ __launch_bounds__(128) void final_kernel(
    const float* __restrict__ X, const float* __restrict__ W,
    const float* __restrict__ b, float* __restrict__ out, int K)
{
    int n = blockIdx.x;
    const float* x = X + (size_t)n * K;

    float acc[NCLS];
    #pragma unroll
    for (int c = 0; c < NCLS; c++) acc[c] = 0.f;

    for (int k = threadIdx.x; k < K; k += 128) {
        float xv = x[k];
        const float* wr = W + (size_t)k * NCLS;
        #pragma unroll
        for (int c = 0; c < NCLS; c++) acc[c] = fmaf(xv, wr[c], acc[c]);
    }
    #pragma unroll
    for (int c = 0; c < NCLS; c++)
        #pragma unroll
        for (int off = 16; off; off >>= 1)
            acc[c] += __shfl_xor_sync(0xffffffffu, acc[c], off);

    __shared__ float sm[4][NCLS];
    int warp = threadIdx.x >> 5, lane = threadIdx.x & 31;
    if (lane == 0) {
        #pragma unroll
        for (int c = 0; c < NCLS; c++) sm[warp][c] = acc[c];
    }
    __syncthreads();
    if (threadIdx.x == 0) {
        float logits[NCLS];
        float m = -1e30f;
        #pragma unroll
        for (int c = 0; c < NCLS; c++) {
            float v = sm[0][c] + sm[1][c] + sm[2][c] + sm[3][c] + b[c];
            v = fmaxf(v, 0.f);
            logits[c] = v;
            m = fmaxf(m, v);
        }
        float ssum = 0.f;
        #pragma unroll
        for (int c = 0; c < NCLS; c++) { logits[c] = expf(logits[c] - m); ssum += logits[c]; }
        float inv = 1.f / ssum;
        #pragma unroll
        for (int c = 0; c < NCLS; c++) out[(size_t)n * NCLS + c] = logits[c] * inv;
    }
}

// ---------------------------------------------------------------------------
// Launch
// ---------------------------------------------------------------------------
static inline int ceil_div(int a, int b) { return (a + b - 1) / b; }

extern "C" void kernel_launch(void* const* d_in, const int* in_sizes, int n_in,
                              void* d_out, int out_size)
{
    const float* x      = (const float*)d_in[0];
    const int*   ei     = (const int*)  d_in[1];
    const float* W0     = (const float*)d_in[2];
    const float* a_src0 = (const float*)d_in[3];
    const float* a_dst0 = (const float*)d_in[4];
    const float* b0     = (const float*)d_in[5];
    const float* W1     = (const float*)d_in[6];
    const float* a_src1 = (const float*)d_in[7];
    const float* a_dst1 = (const float*)d_in[8];
    const float* b1     = (const float*)d_in[9];
    const float* lw1    = (const float*)d_in[10];
    const float* lb1    = (const float*)d_in[11];
    const float* lw2    = (const float*)d_in[12];
    const float* lb2    = (const float*)d_in[13];
    const float* lw3    = (const float*)d_in[14];
    const float* lb3    = (const float*)d_in[15];
    float* out = (float*)d_out;

    const int Nn = in_sizes[0] / F_IN;
    const int E  = in_sizes[1] / 2;
    const int tot = E + Nn;

    float *p_h, *p_out, *p_out2, *p_t1, *p_t2;
    float *p_asrc, *p_adst, *p_emax, *p_denom, *p_escr;
    float *p_wt0, *p_wt1, *p_wt2, *p_wt3;
    cudaGetSymbolAddress((void**)&p_h,     g_h);
    cudaGetSymbolAddress((void**)&p_out,   g_out);
    cudaGetSymbolAddress((void**)&p_out2,  g_out2);
    cudaGetSymbolAddress((void**)&p_t1,    g_t1);
    cudaGetSymbolAddress((void**)&p_t2,    g_t2);
    cudaGetSymbolAddress((void**)&p_asrc,  g_asrc);
    cudaGetSymbolAddress((void**)&p_adst,  g_adst);
    cudaGetSymbolAddress((void**)&p_emax,  g_emax);
    cudaGetSymbolAddress((void**)&p_denom, g_denom);
    cudaGetSymbolAddress((void**)&p_escr,  g_escr);
    cudaGetSymbolAddress((void**)&p_wt0,   g_wt0);
    cudaGetSymbolAddress((void**)&p_wt1,   g_wt1);
    cudaGetSymbolAddress((void**)&p_wt2,   g_wt2);
    cudaGetSymbolAddress((void**)&p_wt3,   g_wt3);

    cudaFuncSetAttribute(mma_gemm, cudaFuncAttributeMaxDynamicSharedMemorySize,
                         GEMM_SMEM_BYTES);

    const int gy = ceil_div(Nn, 128);
    dim3 tb(32, 32);

    // Pre-transpose weights to [N,K]
    transpose_kernel<<<dim3(256 / 32, 128 / 32), tb>>>(W0,  p_wt0, 128, 256);
    transpose_kernel<<<dim3(256 / 32, 256 / 32), tb>>>(W1,  p_wt1, 256, 256);
    transpose_kernel<<<dim3(512 / 32, 256 / 32), tb>>>(lw1, p_wt2, 256, 512);
    transpose_kernel<<<dim3(1024 / 32, 512 / 32), tb>>>(lw2, p_wt3, 512, 1024);

    // ---------------- GAT layer 0 ----------------
    mma_gemm<<<dim3(F0 / 128, gy), 256, GEMM_SMEM_BYTES>>>(
        Nn, F0, F_IN, x, p_wt0, nullptr, p_h, 0);
    alpha_init_kernel<<<ceil_div(Nn * H0 * 32, 256), 256>>>(
        p_h, a_src0, a_dst0, Nn, H0, C0, p_asrc, p_adst, p_emax, p_denom);
    edge_max_kernel<<<ceil_div(tot, 256), 256>>>(ei, E, Nn, H0, p_asrc, p_adst, p_escr, p_emax);
    edge_denom_kernel<<<ceil_div(tot, 256), 256>>>(ei, E, Nn, H0, p_emax, p_escr, p_denom);
    cudaMemsetAsync(p_out, 0, (size_t)Nn * F0 * sizeof(float), 0);
    edge_aggregate_kernel<<<ceil_div(tot * 32, 256), 256>>>(
        ei, E, Nn, H0, 6, p_escr, p_denom, p_h, p_out);
    bias_relu_kernel<<<ceil_div(Nn * F0 / 4, 256), 256>>>((float4*)p_out, b0, Nn * F0 / 4);

    // ---------------- GAT layer 1 ----------------
    mma_gemm<<<dim3(F1 / 128, gy), 256, GEMM_SMEM_BYTES>>>(
        Nn, F1, F0, p_out, p_wt1, nullptr, p_h, 0);
    alpha_init_kernel<<<ceil_div(Nn * H1 * 32, 256), 256>>>(
        p_h, a_src1, a_dst1, Nn, H1, C1, p_asrc, p_adst, p_emax, p_denom);
    edge_max_kernel<<<ceil_div(tot, 256), 256>>>(ei, E, Nn, H1, p_asrc, p_adst, p_escr, p_emax);
    edge_denom_kernel<<<ceil_div(tot, 256), 256>>>(ei, E, Nn, H1, p_emax, p_escr, p_denom);
    cudaMemsetAsync(p_out2, 0, (size_t)Nn * F1 * sizeof(float), 0);
    edge_aggregate_kernel<<<ceil_div(tot * 32, 256), 256>>>(
        ei, E, Nn, H1, 8, p_escr, p_denom, p_h, p_out2);
    bias_relu_kernel<<<ceil_div(Nn * F1 / 4, 256), 256>>>((float4*)p_out2, b1, Nn * F1 / 4);

    // ---------------- MLP ----------------
    mma_gemm<<<dim3(512 / 128, gy), 256, GEMM_SMEM_BYTES>>>(
        Nn, 512, 256, p_out2, p_wt2, lb1, p_t1, 1);
    mma_gemm<<<dim3(1024 / 128, gy), 256, GEMM_SMEM_BYTES>>>(
        Nn, 1024, 512, p_t1, p_wt3, lb2, p_t2, 1);
    final_kernel<<<Nn, 128>>>(p_t2, lw3, lb3, out, 1024);
}